// round 5
// baseline (speedup 1.0000x reference)
#include <cuda_runtime.h>
#include <math.h>

#define NMAX 8192
#define KNB 32
#define CUTOFF2 100.0f
#define CAP 128
#define WARPS_PER_BLK 8
#define NCELL 5
#define NBINS (8 * NCELL * NCELL * NCELL)   // 1000

// scratch (device globals — zero-initialized at load; no allocation allowed)
__device__ float4 g_tp4[NMAX];     // unsorted packed pos (x,y,z,|p|^2)
__device__ int    g_tbin[NMAX];    // bin per original point
__device__ int    g_hist[NBINS];   // zeroed at load; re-zeroed by scan block each run
__device__ int    g_done;          // ticket counter; re-zeroed by scan block each run
__device__ int    g_start[NBINS + 1];
__device__ int    g_cur[NBINS];
__device__ float4 g_sp4[NMAX];     // cell-sorted packed pos
__device__ int    g_sidx[NMAX];    // sorted slot -> original index
__device__ int    g_sbin[NMAX];    // sorted slot -> bin

__device__ __forceinline__ unsigned f2ord(float f) {
    unsigned u = __float_as_uint(f);
    return (u & 0x80000000u) ? ~u : (u | 0x80000000u);
}

// prep + global-atomic histogram + (last block) scan, fused
__global__ void prep_hist_scan_kernel(const float* __restrict__ pos,
                                      const int* __restrict__ batch, int N) {
    int i = blockIdx.x * blockDim.x + threadIdx.x;
    if (i < N) {
        float x = pos[3 * i + 0];
        float y = pos[3 * i + 1];
        float z = pos[3 * i + 2];
        g_tp4[i] = make_float4(x, y, z, x * x + y * y + z * z);
        int cx = min(NCELL - 1, max(0, (int)(x * 0.1f)));
        int cy = min(NCELL - 1, max(0, (int)(y * 0.1f)));
        int cz = min(NCELL - 1, max(0, (int)(z * 0.1f)));
        int bin = batch[i] * (NCELL * NCELL * NCELL) + (cz * NCELL + cy) * NCELL + cx;
        g_tbin[i] = bin;
        atomicAdd(&g_hist[bin], 1);
    }
    __threadfence();
    __syncthreads();
    __shared__ int isLast;
    if (threadIdx.x == 0)
        isLast = (atomicAdd(&g_done, 1) == gridDim.x - 1);
    __syncthreads();
    if (!isLast) return;

    // last block: exclusive scan of the histogram
    __shared__ int buf[2][1024];
    int t = threadIdx.x;
    int val = (t < NBINS) ? atomicAdd(&g_hist[t], 0) : 0;  // coherent read past L1
    buf[0][t] = val;
    __syncthreads();
    int cur = 0;
    for (int off = 1; off < 1024; off <<= 1) {
        int nxt = cur ^ 1;
        int v = buf[cur][t];
        if (t >= off) v += buf[cur][t - off];
        buf[nxt][t] = v;
        __syncthreads();
        cur = nxt;
    }
    int excl = buf[cur][t] - val;
    if (t <= NBINS) g_start[t] = excl;     // g_start[NBINS] == N
    if (t < NBINS) { g_cur[t] = excl; g_hist[t] = 0; }  // reset for next replay
    if (t == 0) g_done = 0;
}

__global__ void scatter_kernel(int N) {
    int i = blockIdx.x * blockDim.x + threadIdx.x;
    if (i >= N) return;
    int bin = g_tbin[i];
    int p = atomicAdd(&g_cur[bin], 1);
    g_sp4[p]  = g_tp4[i];
    g_sidx[p] = i;
    g_sbin[p] = bin;
}

__global__ void __launch_bounds__(WARPS_PER_BLK * 32, 8)
radius_kernel(float* __restrict__ out, int N) {
    __shared__ unsigned long long skey[WARPS_PER_BLK][CAP];
    __shared__ float              swt [WARPS_PER_BLK][CAP];

    const int w    = threadIdx.x >> 5;
    const int lane = threadIdx.x & 31;
    const int u    = blockIdx.x * WARPS_PER_BLK + w;   // sorted slot
    if (u >= N) return;

    const float4 pi = g_sp4[u];
    const int i   = g_sidx[u];
    const int bin = g_sbin[u];
    const int c     = bin % (NCELL * NCELL * NCELL);
    const int bbase = bin - c;
    const int cx = c % NCELL;
    const int cy = (c / NCELL) % NCELL;
    const int cz = c / (NCELL * NCELL);
    const int x0 = max(cx - 1, 0), x1 = min(cx + 1, NCELL - 1);
    const int y0 = max(cy - 1, 0), y1 = min(cy + 1, NCELL - 1);
    const int z0 = max(cz - 1, 0), z1 = min(cz + 1, NCELL - 1);

    // Phase A: scan <=9 contiguous x-strips; compact (key, exact weight)
    int cnt = 0;
    for (int z = z0; z <= z1; z++) {
        for (int y = y0; y <= y1; y++) {
            int blo = bbase + (z * NCELL + y) * NCELL + x0;
            int s = g_start[blo];
            int e = g_start[blo + (x1 - x0) + 1];
            for (int base = s; base < e; base += 32) {
                int t = base + lane;
                bool pass = false;
                float d2 = 0.0f, wt = 0.0f;
                if (t < e && t != u) {
                    float4 pj = g_sp4[t];
                    float dot = pi.x * pj.x + pi.y * pj.y + pi.z * pj.z;
                    d2 = pi.w + pj.w - 2.0f * dot;      // gram-trick: selection like ref
                    pass = (d2 <= CUTOFF2);
                    if (pass) {
                        float dx = pj.x - pi.x, dy = pj.y - pi.y, dz = pj.z - pi.z;
                        float sq = dx * dx + dy * dy + dz * dz;
                        wt = (sq > 0.0f) ? sqrtf(sq) : 0.0f;  // exact weight like ref
                    }
                }
                unsigned m = __ballot_sync(0xffffffffu, pass);
                if (pass) {
                    int idx = cnt + __popc(m & ((1u << lane) - 1u));
                    if (idx < CAP) {
                        int j = g_sidx[t];   // original index = tie-break key
                        skey[w][idx] = ((unsigned long long)f2ord(d2) << 32) | (unsigned)j;
                        swt [w][idx] = wt;
                    }
                }
                cnt += __popc(m);
            }
        }
    }
    if (cnt > CAP) cnt = CAP;
    __syncwarp();

    const long long E = (long long)N * KNB + N;
    float* __restrict__ orow = out;
    float* __restrict__ ocol = out + E;
    float* __restrict__ owt  = out + 2 * E;
    float* __restrict__ omk  = out + 3 * E;
    const long long bo = (long long)i * KNB;

    // col is always i; padded slots (k >= cnt): row=0, w=0, mask=0
    {
        int k = lane;   // KNB == 32
        ocol[bo + k] = (float)i;
        if (k >= cnt) { orow[bo + k] = 0.0f; owt[bo + k] = 0.0f; omk[bo + k] = 0.0f; }
    }

    // Phase B: rank-by-counting; rank == output slot (== top_k order)
    for (int cc = lane; cc < cnt; cc += 32) {
        unsigned long long key = skey[w][cc];
        int rank = 0;
        for (int t = 0; t < cnt; t++) rank += (skey[w][t] < key);
        if (rank < KNB) {
            int j = (int)(unsigned)(key & 0xffffffffu);
            orow[bo + rank] = (float)j;
            owt [bo + rank] = swt[w][cc];
            omk [bo + rank] = 1.0f;
        }
    }

    // self-loop at N*K + i
    if (lane == 0) {
        long long si = (long long)N * KNB + i;
        orow[si] = (float)i;
        ocol[si] = (float)i;
        owt [si] = 0.0f;
        omk [si] = 1.0f;
    }
}

extern "C" void kernel_launch(void* const* d_in, const int* in_sizes, int n_in,
                              void* d_out, int out_size) {
    const float* pos   = (const float*)d_in[0];
    const int*   batch = (const int*)d_in[1];
    float* out = (float*)d_out;
    int N = in_sizes[0] / 3;   // 8192

    prep_hist_scan_kernel<<<(N + 1023) / 1024, 1024>>>(pos, batch, N);
    scatter_kernel<<<(N + 255) / 256, 256>>>(N);
    radius_kernel<<<(N + WARPS_PER_BLK - 1) / WARPS_PER_BLK, WARPS_PER_BLK * 32>>>(out, N);
}

// round 11
// speedup vs baseline: 1.0297x; 1.0297x over previous
#include <cuda_runtime.h>
#include <math.h>

#define NMAX 8192
#define KNB 32
#define CUTOFF2 100.0f
#define CAP 128
#define WARPS_PER_BLK 8
#define NCELL 5
#define NBINS (8 * NCELL * NCELL * NCELL)   // 1000

// scratch (device globals — zero-initialized at load; g_hist/g_off re-zeroed each run by K3)
__device__ float4 g_tp4[NMAX];     // unsorted packed pos (x,y,z,|p|^2)
__device__ int    g_tbin[NMAX];    // bin per original point
__device__ int    g_hist[NBINS];
__device__ int    g_off[NBINS];
__device__ int    g_start[NBINS + 1];
__device__ float4 g_sp4[NMAX];     // cell-sorted packed pos
__device__ int    g_sidx[NMAX];    // sorted slot -> original index
__device__ int    g_sbin[NMAX];    // sorted slot -> bin

__device__ __forceinline__ unsigned f2ord(float f) {
    unsigned u = __float_as_uint(f);
    return (u & 0x80000000u) ? ~u : (u | 0x80000000u);
}

// K1: pack positions + histogram
__global__ void prep_kernel(const float* __restrict__ pos,
                            const int* __restrict__ batch, int N) {
    int i = blockIdx.x * blockDim.x + threadIdx.x;
    if (i >= N) return;
    float x = pos[3 * i + 0];
    float y = pos[3 * i + 1];
    float z = pos[3 * i + 2];
    g_tp4[i] = make_float4(x, y, z, x * x + y * y + z * z);
    int cx = min(NCELL - 1, max(0, (int)(x * 0.1f)));
    int cy = min(NCELL - 1, max(0, (int)(y * 0.1f)));
    int cz = min(NCELL - 1, max(0, (int)(z * 0.1f)));
    int bin = batch[i] * (NCELL * NCELL * NCELL) + (cz * NCELL + cy) * NCELL + cx;
    g_tbin[i] = bin;
    atomicAdd(&g_hist[bin], 1);
}

// K2: every block redundantly scans the histogram in smem, then scatters its points
__global__ void scan_scatter_kernel(int N) {
    __shared__ int partial[256];
    __shared__ int sstart[1024];
    const int tid = threadIdx.x;

    // block-local exclusive scan of g_hist (values identical in every block)
    const int b0 = tid * 4;               // 256*4 = 1024 >= NBINS
    int v0 = 0, v1 = 0, v2 = 0, v3 = 0;
    if (b0 < NBINS) {
        v0 = g_hist[b0];     v1 = g_hist[b0 + 1];
        v2 = g_hist[b0 + 2]; v3 = g_hist[b0 + 3];
    }
    const int sum = v0 + v1 + v2 + v3;
    partial[tid] = sum;
    __syncthreads();
    for (int off = 1; off < 256; off <<= 1) {
        int x = partial[tid];
        int y = (tid >= off) ? partial[tid - off] : 0;
        __syncthreads();
        partial[tid] = x + y;
        __syncthreads();
    }
    const int excl = partial[tid] - sum;
    sstart[b0]     = excl;
    sstart[b0 + 1] = excl + v0;
    sstart[b0 + 2] = excl + v0 + v1;
    sstart[b0 + 3] = excl + v0 + v1 + v2;
    if (b0 < NBINS) {                      // duplicate identical writes: benign
        g_start[b0]     = sstart[b0];
        g_start[b0 + 1] = sstart[b0 + 1];
        g_start[b0 + 2] = sstart[b0 + 2];
        g_start[b0 + 3] = sstart[b0 + 3];
    }
    if (tid == 0 && blockIdx.x == 0) g_start[NBINS] = N;
    __syncthreads();

    // scatter this block's points
    int i = blockIdx.x * blockDim.x + tid;
    if (i < N) {
        int bin = g_tbin[i];
        int p = sstart[bin] + atomicAdd(&g_off[bin], 1);
        g_sp4[p]  = g_tp4[i];
        g_sidx[p] = i;
        g_sbin[p] = bin;
    }
}

// K3: radius graph (warp per node) + reset counters for next graph replay
__global__ void __launch_bounds__(WARPS_PER_BLK * 32, 8)
radius_kernel(float* __restrict__ out, int N) {
    __shared__ unsigned long long skey[WARPS_PER_BLK][CAP];
    __shared__ float              swt [WARPS_PER_BLK][CAP];

    // reset scratch counters for the next replay (nothing in K3 reads them)
    {
        int r = blockIdx.x * blockDim.x + threadIdx.x;
        if (r < NBINS) { g_hist[r] = 0; g_off[r] = 0; }
    }

    const int w    = threadIdx.x >> 5;
    const int lane = threadIdx.x & 31;
    const int u    = blockIdx.x * WARPS_PER_BLK + w;   // sorted slot
    if (u >= N) return;

    const float4 pi = g_sp4[u];
    const int i   = g_sidx[u];
    const int bin = g_sbin[u];
    const int c     = bin % (NCELL * NCELL * NCELL);
    const int bbase = bin - c;
    const int cx = c % NCELL;
    const int cy = (c / NCELL) % NCELL;
    const int cz = c / (NCELL * NCELL);
    const int x0 = max(cx - 1, 0), x1 = min(cx + 1, NCELL - 1);
    const int y0 = max(cy - 1, 0), y1 = min(cy + 1, NCELL - 1);
    const int z0 = max(cz - 1, 0), z1 = min(cz + 1, NCELL - 1);

    // Phase A: scan <=9 contiguous x-strips; compact (key, exact weight)
    int cnt = 0;
    for (int z = z0; z <= z1; z++) {
        for (int y = y0; y <= y1; y++) {
            int blo = bbase + (z * NCELL + y) * NCELL + x0;
            int s = g_start[blo];
            int e = g_start[blo + (x1 - x0) + 1];
            for (int base = s; base < e; base += 32) {
                int t = base + lane;
                bool pass = false;
                float d2 = 0.0f, wt = 0.0f;
                if (t < e && t != u) {
                    float4 pj = g_sp4[t];
                    float dot = pi.x * pj.x + pi.y * pj.y + pi.z * pj.z;
                    d2 = pi.w + pj.w - 2.0f * dot;      // gram-trick: selection like ref
                    pass = (d2 <= CUTOFF2);
                    if (pass) {
                        float dx = pj.x - pi.x, dy = pj.y - pi.y, dz = pj.z - pi.z;
                        float sq = dx * dx + dy * dy + dz * dz;
                        wt = (sq > 0.0f) ? sqrtf(sq) : 0.0f;  // exact weight like ref
                    }
                }
                unsigned m = __ballot_sync(0xffffffffu, pass);
                if (pass) {
                    int idx = cnt + __popc(m & ((1u << lane) - 1u));
                    if (idx < CAP) {
                        int j = g_sidx[t];   // original index = tie-break key
                        skey[w][idx] = ((unsigned long long)f2ord(d2) << 32) | (unsigned)j;
                        swt [w][idx] = wt;
                    }
                }
                cnt += __popc(m);
            }
        }
    }
    if (cnt > CAP) cnt = CAP;
    __syncwarp();

    const long long E = (long long)N * KNB + N;
    float* __restrict__ orow = out;
    float* __restrict__ ocol = out + E;
    float* __restrict__ owt  = out + 2 * E;
    float* __restrict__ omk  = out + 3 * E;
    const long long bo = (long long)i * KNB;

    // col is always i; padded slots (k >= cnt): row=0, w=0, mask=0
    {
        int k = lane;   // KNB == 32
        ocol[bo + k] = (float)i;
        if (k >= cnt) { orow[bo + k] = 0.0f; owt[bo + k] = 0.0f; omk[bo + k] = 0.0f; }
    }

    // Phase B: rank-by-counting; rank == output slot (== top_k order)
    for (int cc = lane; cc < cnt; cc += 32) {
        unsigned long long key = skey[w][cc];
        int rank = 0;
        for (int t = 0; t < cnt; t++) rank += (skey[w][t] < key);
        if (rank < KNB) {
            int j = (int)(unsigned)(key & 0xffffffffu);
            orow[bo + rank] = (float)j;
            owt [bo + rank] = swt[w][cc];
            omk [bo + rank] = 1.0f;
        }
    }

    // self-loop at N*K + i
    if (lane == 0) {
        long long si = (long long)N * KNB + i;
        orow[si] = (float)i;
        ocol[si] = (float)i;
        owt [si] = 0.0f;
        omk [si] = 1.0f;
    }
}

extern "C" void kernel_launch(void* const* d_in, const int* in_sizes, int n_in,
                              void* d_out, int out_size) {
    const float* pos   = (const float*)d_in[0];
    const int*   batch = (const int*)d_in[1];
    float* out = (float*)d_out;
    int N = in_sizes[0] / 3;   // 8192

    prep_kernel<<<(N + 255) / 256, 256>>>(pos, batch, N);
    scan_scatter_kernel<<<(N + 255) / 256, 256>>>(N);
    radius_kernel<<<(N + WARPS_PER_BLK - 1) / WARPS_PER_BLK, WARPS_PER_BLK * 32>>>(out, N);
}